// round 13
// baseline (speedup 1.0000x reference)
#include <cuda_runtime.h>
#include <math.h>

#define BINSIZE      200
#define BINWIDTH     500
#define N_CLUSTERS   20
#define N_ROI_MAX    200

// Precomputed log-density table: [n_roi, n_clusters, BINWIDTH]  (8MB)
__device__ float g_heights[N_ROI_MAX * N_CLUSTERS * BINWIDTH];

// ---------------------------------------------------------------------------
// Kernel 1: heights build only (one warp per (roi,cluster) row).
// Triggers programmatic launch completion at block start so the gather
// kernel can run its full preamble (streams + label gathers + index math)
// while this kernel runs.
// ---------------------------------------------------------------------------
__global__ void __launch_bounds__(256) build_kernel(
    const float* __restrict__ baseline,
    const float* __restrict__ delta,
    const int*   __restrict__ regions_oi,
    int n_rows, int n_clusters)
{
#if __CUDA_ARCH__ >= 900
    cudaTriggerProgrammaticLaunchCompletion();
#endif
    const int warp = (int)blockIdx.x * 8 + ((int)threadIdx.x >> 5);
    if (warp >= n_rows) return;
    const int lane = threadIdx.x & 31;
    const int roi = warp / n_clusters;
    const int cl  = warp - roi * n_clusters;
    const int region = regions_oi[roi];

    const float4* __restrict__ b4 = (const float4*)(baseline + (long long)region * BINWIDTH);
    const float4* __restrict__ d4 = (const float4*)(delta + ((long long)region * n_clusters + cl) * BINWIDTH);

    float4 v[4];
    float m = -INFINITY;
    #pragma unroll
    for (int it = 0; it < 4; it++) {
        const int idx = lane + it * 32;
        if (idx < 125) {
            float4 a = b4[idx];
            float4 d = d4[idx];
            v[it].x = a.x + d.x; v[it].y = a.y + d.y;
            v[it].z = a.z + d.z; v[it].w = a.w + d.w;
            m = fmaxf(m, fmaxf(fmaxf(v[it].x, v[it].y), fmaxf(v[it].z, v[it].w)));
        }
    }
    #pragma unroll
    for (int o = 16; o > 0; o >>= 1)
        m = fmaxf(m, __shfl_xor_sync(0xffffffffu, m, o));

    float s = 0.0f;
    #pragma unroll
    for (int it = 0; it < 4; it++) {
        const int idx = lane + it * 32;
        if (idx < 125) {
            s += __expf(v[it].x - m) + __expf(v[it].y - m)
               + __expf(v[it].z - m) + __expf(v[it].w - m);
        }
    }
    #pragma unroll
    for (int o = 16; o > 0; o >>= 1)
        s += __shfl_xor_sync(0xffffffffu, s, o);

    const float sub = m + __logf(s) + logf((float)BINSIZE);

    float4* __restrict__ o4 = (float4*)(g_heights + (long long)warp * BINWIDTH);
    #pragma unroll
    for (int it = 0; it < 4; it++) {
        const int idx = lane + it * 32;
        if (idx < 125) {
            float4 h;
            h.x = v[it].x - sub; h.y = v[it].y - sub;
            h.z = v[it].z - sub; h.w = v[it].w - sub;
            o4[idx] = h;
        }
    }
}

// ---------------------------------------------------------------------------
// Kernel 2: gather, warp-cooperative lane-contiguous layout (128 frags/warp).
// PDL preamble resolves EVERYTHING except the heights gather: streaming
// loads, label gathers (directly from the int32 input — independent of
// build), and the full heights index. After GridDependencySynchronize only
// one one-deep gather + store remains.
// ---------------------------------------------------------------------------
__global__ void __launch_bounds__(256) gather_kernel(
    const int*   __restrict__ coords,      // [n, 2]
    const int*   __restrict__ lrix,        // [n]
    const int*   __restrict__ lcix,        // [n]
    const int*   __restrict__ labels,      // [n_cells] int32
    const float* __restrict__ inside,      // [1]
    float*       __restrict__ out,         // [n, 2]
    int n, int n_clusters)
{
    const int warp_g = (blockIdx.x * blockDim.x + threadIdx.x) >> 5;
    const int lane   = threadIdx.x & 31;
    const int fbase  = warp_g * 128;

    const float x    = inside[0];
    const float l1p  = log1pf(expf(-x));
    const float lpIn  = -l1p     - logf((float)BINWIDTH);
    const float lpOut = -x - l1p - logf((float)(100000 - BINWIDTH));

    if (fbase >= n) {
#if __CUDA_ARCH__ >= 900
        cudaGridDependencySynchronize();
#endif
        return;
    }

    if (fbase + 128 <= n) {
        const int vbase = warp_g * 64;
        // ---- preamble (overlaps build kernel under PDL) ----
        const int4 cv0 = __ldcs((const int4*)coords + vbase + lane);
        const int4 cv1 = __ldcs((const int4*)coords + vbase + 32 + lane);
        const int2 q01 = __ldcs((const int2*)lcix + vbase + lane);
        const int2 q23 = __ldcs((const int2*)lcix + vbase + 32 + lane);
        const int2 r01 = __ldcs((const int2*)lrix + vbase + lane);
        const int2 r23 = __ldcs((const int2*)lrix + vbase + 32 + lane);

        // label gathers: independent of build outputs -> still preamble
        const int lab0 = __ldg(&labels[q01.x]);
        const int lab1 = __ldg(&labels[q01.y]);
        const int lab2 = __ldg(&labels[q23.x]);
        const int lab3 = __ldg(&labels[q23.y]);

        const int bl0 = (int)((unsigned)cv0.x / BINSIZE), br0 = (int)((unsigned)cv0.y / BINSIZE);
        const int bl1 = (int)((unsigned)cv0.z / BINSIZE), br1 = (int)((unsigned)cv0.w / BINSIZE);
        const int bl2 = (int)((unsigned)cv1.x / BINSIZE), br2 = (int)((unsigned)cv1.y / BINSIZE);
        const int bl3 = (int)((unsigned)cv1.z / BINSIZE), br3 = (int)((unsigned)cv1.w / BINSIZE);

        const int i0 = (r01.x * n_clusters + lab0) * BINWIDTH + bl0;
        const int i1 = (r01.y * n_clusters + lab1) * BINWIDTH + bl1;
        const int i2 = (r23.x * n_clusters + lab2) * BINWIDTH + bl2;
        const int i3 = (r23.y * n_clusters + lab3) * BINWIDTH + bl3;

        // ---- wait for the heights table, then one-deep gather ----
#if __CUDA_ARCH__ >= 900
        cudaGridDependencySynchronize();
#endif
        const float L0 = __ldcg(&g_heights[i0]);
        const float L1 = __ldcg(&g_heights[i1]);
        const float L2 = __ldcg(&g_heights[i2]);
        const float L3 = __ldcg(&g_heights[i3]);

        float4 o0, o1;
        o0.x = L0; o0.y = (bl0 == br0) ? lpIn : lpOut;
        o0.z = L1; o0.w = (bl1 == br1) ? lpIn : lpOut;
        o1.x = L2; o1.y = (bl2 == br2) ? lpIn : lpOut;
        o1.z = L3; o1.w = (bl3 == br3) ? lpIn : lpOut;
        __stcs((float4*)out + vbase + lane,      o0);
        __stcs((float4*)out + vbase + 32 + lane, o1);
    } else {
        // tail warp: scalar per-fragment
#if __CUDA_ARCH__ >= 900
        cudaGridDependencySynchronize();
#endif
        for (int i = fbase + lane; i < n; i += 32) {
            const int cx = coords[i * 2 + 0];
            const int cy = coords[i * 2 + 1];
            const int bl = (int)((unsigned)cx / BINSIZE), br = (int)((unsigned)cy / BINSIZE);
            const int lab = labels[lcix[i]];
            const int rg = lrix[i];
            out[i * 2 + 0] = __ldcg(&g_heights[(rg * n_clusters + lab) * BINWIDTH + bl]);
            out[i * 2 + 1] = (bl == br) ? lpIn : lpOut;
        }
    }
}

// ---------------------------------------------------------------------------
extern "C" void kernel_launch(void* const* d_in, const int* in_sizes, int n_in,
                              void* d_out, int out_size)
{
    const float* baseline = (const float*)d_in[0];
    const float* delta    = (const float*)d_in[1];
    const float* inside   = (const float*)d_in[2];
    const int*   regions  = (const int*)d_in[3];
    const int*   coords   = (const int*)d_in[4];
    const int*   lrix     = (const int*)d_in[5];
    const int*   lcix     = (const int*)d_in[6];
    const int*   labels   = (const int*)d_in[7];
    float*       out      = (float*)d_out;

    const int n_roi      = in_sizes[3];
    const int n          = in_sizes[5];
    const int n_regions  = in_sizes[0] / BINWIDTH;
    const int n_clusters = (n_regions > 0) ? (in_sizes[1] / (n_regions * BINWIDTH)) : N_CLUSTERS;

    const int n_rows    = n_roi * n_clusters;
    const int rowBlocks = (n_rows + 7) / 8;
    build_kernel<<<rowBlocks, 256>>>(baseline, delta, regions, n_rows, n_clusters);

    const int warps  = (n + 127) / 128;
    const int blocks = (warps + 7) / 8;       // 8 warps (256 threads) per block

    cudaLaunchConfig_t cfg = {};
    cfg.gridDim  = dim3((unsigned)blocks, 1, 1);
    cfg.blockDim = dim3(256, 1, 1);
    cfg.dynamicSmemBytes = 0;
    cfg.stream = 0;
    cudaLaunchAttribute at[1];
    at[0].id = cudaLaunchAttributeProgrammaticStreamSerialization;
    at[0].val.programmaticStreamSerializationAllowed = 1;
    cfg.attrs = at;
    cfg.numAttrs = 1;
    cudaError_t e = cudaLaunchKernelEx(&cfg, gather_kernel,
                                       coords, lrix, lcix, labels, inside, out,
                                       n, n_clusters);
    if (e != cudaSuccess) {
        gather_kernel<<<blocks, 256>>>(coords, lrix, lcix, labels, inside, out,
                                       n, n_clusters);
    }
}